// round 14
// baseline (speedup 1.0000x reference)
#include <cuda_runtime.h>
#include <cuda_fp16.h>
#include <stdint.h>

// ---- SOM constants (match reference) ----
#define NODES 4096
#define FEATS 256
#define BATCH 1024
#define SIGMA_F 70.4f        // max(M,N) * 1.1
#define TOTAL_ITER_F 100000.0f

typedef unsigned long long u64;

// ---- device scratch (no allocations allowed) ----
__device__ u64   g_best[BATCH];
__device__ float g_w2[NODES];
__device__ float g_params[3];   // [0]=lr, [1]=1/(2 r^2), [2]=r^2
__device__ __align__(16) __half g_xh[BATCH * FEATS];
__device__ __align__(16) __half g_xl[BATCH * FEATS];
__device__ __align__(16) __half g_wh[NODES * FEATS];
__device__ __align__(16) __half g_wl[NODES * FEATS];
__device__ __align__(16) __half g_xt[FEATS * BATCH];   // x transposed, fp16

// ---- PTX helpers ----
__device__ __forceinline__ uint32_t smem_u32(const void* p) {
    uint32_t a;
    asm("{ .reg .u64 t; cvta.to.shared.u64 t, %1; cvt.u32.u64 %0, t; }"
        : "=r"(a) : "l"(p));
    return a;
}
__device__ __forceinline__ void cp16(uint32_t dst, const void* src) {
    asm volatile("cp.async.cg.shared.global [%0], [%1], 16;"
                 :: "r"(dst), "l"(src));
}
#define CP_COMMIT() asm volatile("cp.async.commit_group;" ::: "memory")
#define CP_WAIT0()  asm volatile("cp.async.wait_group 0;" ::: "memory")

__device__ __forceinline__ void ldsm4(uint32_t* r, uint32_t addr) {
    asm volatile("ldmatrix.sync.aligned.m8n8.x4.shared.b16 {%0,%1,%2,%3}, [%4];"
                 : "=r"(r[0]), "=r"(r[1]), "=r"(r[2]), "=r"(r[3]) : "r"(addr));
}
__device__ __forceinline__ void mma16816(float* c, const uint32_t* a,
                                         const uint32_t* b) {
    asm volatile(
        "mma.sync.aligned.m16n8k16.row.col.f32.f16.f16.f32 "
        "{%0,%1,%2,%3}, {%4,%5,%6,%7}, {%8,%9}, {%0,%1,%2,%3};"
        : "+f"(c[0]), "+f"(c[1]), "+f"(c[2]), "+f"(c[3])
        : "r"(a[0]), "r"(a[1]), "r"(a[2]), "r"(a[3]), "r"(b[0]), "r"(b[1]));
}
__device__ __forceinline__ u64 packkey(float d, int n) {
    unsigned u = __float_as_uint(d);
    u = (u & 0x80000000u) ? ~u : (u | 0x80000000u);
    return ((u64)u << 32) | (unsigned)n;
}

// ============================================================
// K1: fused prep (grid-704 layout, proven 6.3us).
// ============================================================
__device__ __forceinline__ void split8(const float* src, __half* hi, __half* lo,
                                       float* sumsq) {
    float4 va = ((const float4*)src)[0];
    float4 vb = ((const float4*)src)[1];
    float f[8] = {va.x, va.y, va.z, va.w, vb.x, vb.y, vb.z, vb.w};
    __half2 h2[4], l2[4];
    float s = 0.0f;
    #pragma unroll
    for (int i = 0; i < 4; i++) {
        float a = f[2 * i], b = f[2 * i + 1];
        s += a * a + b * b;
        float ha = __half2float(__float2half_rn(a));
        float hb = __half2float(__float2half_rn(b));
        h2[i] = __floats2half2_rn(ha, hb);
        l2[i] = __floats2half2_rn(a - ha, b - hb);
    }
    *(uint4*)hi = *(uint4*)h2;
    *(uint4*)lo = *(uint4*)l2;
    if (sumsq) *sumsq = s;
}

__global__ void __launch_bounds__(256) k_prep_all(const float* __restrict__ x,
                                                  const float* __restrict__ w,
                                                  const int* __restrict__ iter) {
    int bid = blockIdx.x;
    int t = threadIdx.x;
    int warp = t >> 5, lane = t & 31;

    if (bid < 512) {                       // w rows: split + w2
        int n = bid * 8 + warp;
        int c = lane * 8;
        float s;
        split8(w + (size_t)n * FEATS + c, g_wh + n * FEATS + c,
               g_wl + n * FEATS + c, &s);
        #pragma unroll
        for (int o = 16; o; o >>= 1) s += __shfl_xor_sync(0xFFFFFFFFu, s, o);
        if (lane == 0) g_w2[n] = s;
    } else if (bid < 640) {                // x rows: split
        int r = (bid - 512) * 8 + warp;
        int c = lane * 8;
        split8(x + (size_t)r * FEATS + c, g_xh + r * FEATS + c,
               g_xl + r * FEATS + c, nullptr);
    } else {                               // x transpose tiles
        __shared__ float s[64][65];
        int bx2 = bid - 640;
        if (bx2 < 4) {
            g_best[bx2 * 256 + t] = 0xFFFFFFFFFFFFFFFFull;
            if (bx2 == 0 && t == 0) {
                float lambda_g = TOTAL_ITER_F / SIGMA_F;
                float decay    = expf(-(float)iter[0] / lambda_g);
                float radius   = SIGMA_F * decay + 1e-6f;
                g_params[0] = 0.5f * decay;
                g_params[1] = 1.0f / (2.0f * radius * radius);
                g_params[2] = radius * radius;
            }
        }
        int b0 = (bx2 >> 2) * 64, d0 = (bx2 & 3) * 64;
        #pragma unroll
        for (int q = 0; q < 16; q++) {
            int e = q * 256 + t;
            int br = e >> 6, dc = e & 63;
            s[br][dc] = x[(size_t)(b0 + br) * FEATS + d0 + dc];
        }
        __syncthreads();
        #pragma unroll
        for (int q = 0; q < 16; q++) {
            int e = q * 256 + t;
            int dr = e >> 6, bc = e & 63;
            g_xt[(size_t)(d0 + dr) * BATCH + b0 + bc] = __float2half_rn(s[bc][dr]);
        }
    }
}

// ============================================================
// K2: BMU GEMM via HMMA (proven, unchanged).
// ============================================================
#define ASZ (128 * 144)
#define BSZ (128 * 144)
#define OFF_A 1024
#define OFF_B (1024 + 2 * ASZ)
#define SM_BMU (OFF_B + 2 * BSZ)

__device__ __forceinline__ void stage_bmu(uint32_t sb, int buf, int ch,
                                          int m0, int n0, int t) {
    int term = ch >> 2;
    int kk = (ch & 3) * 64;
    const __half* asrc = (term < 2) ? g_xh : g_xl;
    const __half* bsrc = (term == 1) ? g_wl : g_wh;
    uint32_t adst = sb + OFF_A + buf * ASZ;
    uint32_t bdst = sb + OFF_B + buf * BSZ;
    #pragma unroll
    for (int q = 0; q < 4; q++) {
        int g = t + 256 * q; int r = g >> 3, c = g & 7;
        cp16(adst + r * 144 + c * 16, asrc + (size_t)(m0 + r) * FEATS + kk + c * 8);
        cp16(bdst + r * 144 + c * 16, bsrc + (size_t)(n0 + r) * FEATS + kk + c * 8);
    }
    CP_COMMIT();
}

__global__ void __launch_bounds__(256, 2) k_bmu() {
    extern __shared__ char sm[];
    uint32_t sb = smem_u32(sm);
    float* w2s = (float*)sm;
    int t = threadIdx.x, lane = t & 31, warp = t >> 5;
    int wm = warp >> 1, wn = warp & 1;     // 4m x 2n warp grid
    int n0 = blockIdx.x * 128;
    int m0 = blockIdx.y * 128;

    if (t < 128) w2s[t] = g_w2[n0 + t];

    float c[2][8][4];
    #pragma unroll
    for (int i = 0; i < 2; i++)
        #pragma unroll
        for (int j = 0; j < 8; j++)
            #pragma unroll
            for (int q = 0; q < 4; q++) c[i][j][q] = 0.0f;

    uint32_t aoff = (uint32_t)((lane & 15) * 144 + (lane >> 4) * 16);
    uint32_t boff = (uint32_t)(((lane & 7) + ((lane >> 4) << 3)) * 144
                               + (((lane >> 3) & 1) << 4));

    stage_bmu(sb, 0, 0, m0, n0, t);
    for (int ch = 0; ch < 12; ch++) {
        CP_WAIT0();
        __syncthreads();   // data visible + prior-iter reads of buf^1 done
        if (ch + 1 < 12) stage_bmu(sb, (ch + 1) & 1, ch + 1, m0, n0, t);

        uint32_t Ab = sb + OFF_A + (ch & 1) * ASZ + (wm * 32) * 144 + aoff;
        uint32_t Bb = sb + OFF_B + (ch & 1) * BSZ + (wn * 64) * 144 + boff;
        #pragma unroll
        for (int k16 = 0; k16 < 4; k16++) {
            uint32_t a[2][4], b[4][4];
            #pragma unroll
            for (int im = 0; im < 2; im++)
                ldsm4(a[im], Ab + im * 16 * 144 + k16 * 32);
            #pragma unroll
            for (int j2 = 0; j2 < 4; j2++)
                ldsm4(b[j2], Bb + j2 * 16 * 144 + k16 * 32);
            #pragma unroll
            for (int im = 0; im < 2; im++)
                #pragma unroll
                for (int j2 = 0; j2 < 4; j2++) {
                    mma16816(c[im][2 * j2],     a[im], b[j2]);
                    mma16816(c[im][2 * j2 + 1], a[im], b[j2] + 2);
                }
        }
    }

    // fused argmin epilogue
    #pragma unroll
    for (int im = 0; im < 2; im++) {
        #pragma unroll
        for (int h = 0; h < 2; h++) {
            float best = __int_as_float(0x7F800000);
            int bestn = 0;
            #pragma unroll
            for (int j8 = 0; j8 < 8; j8++) {
                int nl = wn * 64 + j8 * 8 + 2 * (lane & 3);
                float v0 = w2s[nl]     - 2.0f * c[im][j8][2 * h];
                float v1 = w2s[nl + 1] - 2.0f * c[im][j8][2 * h + 1];
                if (v0 < best) { best = v0; bestn = nl; }
                if (v1 < best) { best = v1; bestn = nl + 1; }
            }
            #pragma unroll
            for (int o = 1; o <= 2; o <<= 1) {
                float od = __shfl_xor_sync(0xFFFFFFFFu, best, o);
                int   on = __shfl_xor_sync(0xFFFFFFFFu, bestn, o);
                if (od < best || (od == best && on < bestn)) { best = od; bestn = on; }
            }
            if ((lane & 3) == 0) {
                int m = m0 + wm * 32 + im * 16 + h * 8 + (lane >> 2);
                atomicMin(&g_best[m], packkey(best, n0 + bestn));
            }
        }
    }
}

// ============================================================
// K3: update GEMM (R7 champion structure: 32n x 128d, grid 256,
// 2 CTAs/SM, gen-AHEAD L overlapped with compute, 2-stage X pipe).
// ONE delta vs R7: gen_L uses separable-exp smem tables + u8 bmu
// coords instead of g_best LDG + __expf.
// ============================================================
__global__ void __launch_bounds__(256, 2) k_update(const float* __restrict__ w,
                                                   float* __restrict__ out,
                                                   int out_size) {
    __shared__ float s_sm[32];
    __shared__ float s_part[256];
    __shared__ __align__(16) __half Ls[2][32 * 72];
    __shared__ __align__(16) __half Xs[2][128 * 72];
    __shared__ float tabA[64], tabB[64];
    __shared__ uint8_t sbi[BATCH], sbj[BATCH];

    uint32_t sbL = smem_u32(Ls);
    uint32_t sbX = smem_u32(Xs);

    int t = threadIdx.x, lane = t & 31, warp = t >> 5;
    int wn = warp >> 2, wd = warp & 3;     // 2n x 4d warp grid
    int bx = blockIdx.x;
    int n0 = (bx >> 1) * 32;
    int d0 = (bx & 1) * 128;

    float lr = g_params[0], inv2r2 = g_params[1], r2 = g_params[2];

    // table + bmu-coord prologue (the ONLY change vs R7)
    if (t < 64) {
        float e = __expf(-(float)(t * t) * inv2r2);
        tabA[t] = lr * e;
        tabB[t] = e;
    }
    #pragma unroll
    for (int q = 0; q < 4; q++) {
        int b = t + 256 * q;
        int bmu = (int)(unsigned)(g_best[b] & 0xFFFFFFFFull);
        sbi[b] = (uint8_t)(bmu >> 6);
        sbj[b] = (uint8_t)(bmu & 63);
    }

    int n_l = t & 31;
    int gn = n0 + n_l;
    int ni = gn >> 6, nj = gn & 63;
    int bgrp = t >> 5;          // 0..7
    float s_local = 0.0f;

    float c[4][4];
    #pragma unroll
    for (int j = 0; j < 4; j++)
        #pragma unroll
        for (int q = 0; q < 4; q++) c[j][q] = 0.0f;

    uint32_t aoff = (uint32_t)((lane & 15) * 144 + (lane >> 4) * 16);
    uint32_t boff = (uint32_t)(((lane & 7) + ((lane >> 4) << 3)) * 144
                               + (((lane >> 3) & 1) << 4));

    // L generator for chunk ch into buffer buf (thread n = t&31, b = bgrp+8j)
    auto gen_L = [&](int ch, int buf) {
        int bc0 = ch * 64;
        #pragma unroll
        for (int j = 0; j < 8; j++) {
            int bb = bgrp + 8 * j;
            int di = ni - (int)sbi[bc0 + bb];
            int dj = nj - (int)sbj[bc0 + bb];
            float d2 = (float)(di * di + dj * dj);
            float v = (d2 <= r2) ? tabA[abs(di)] * tabB[abs(dj)] : 0.0f;
            Ls[buf][n_l * 72 + bb] = __float2half_rn(v);
            s_local += v;
        }
    };

    // prologue: stage X(0); sync (tables/coords visible); generate L(0)
    #pragma unroll
    for (int q = 0; q < 4; q++) {
        int g = t + 256 * q; int r = g >> 3, cc = g & 7;
        cp16(sbX + r * 144 + cc * 16, g_xt + (size_t)(d0 + r) * BATCH + cc * 8);
    }
    CP_COMMIT();
    __syncthreads();
    gen_L(0, 0);

    for (int ch = 0; ch < 16; ch++) {
        CP_WAIT0();
        __syncthreads();   // X(ch)+L(ch) visible; prior reads of buf^1 done
        if (ch + 1 < 16) {
            uint32_t xdst = sbX + ((ch + 1) & 1) * (128 * 144);
            #pragma unroll
            for (int q = 0; q < 4; q++) {
                int g = t + 256 * q; int r = g >> 3, cc = g & 7;
                cp16(xdst + r * 144 + cc * 16,
                     g_xt + (size_t)(d0 + r) * BATCH + (ch + 1) * 64 + cc * 8);
            }
            CP_COMMIT();
            gen_L(ch + 1, (ch + 1) & 1);   // overlapped with compute below
        }

        uint32_t Ab = sbL + (ch & 1) * (32 * 144) + (wn * 16) * 144 + aoff;
        uint32_t Bb = sbX + (ch & 1) * (128 * 144) + (wd * 32) * 144 + boff;
        #pragma unroll
        for (int k16 = 0; k16 < 4; k16++) {
            uint32_t a[4], b[2][4];
            ldsm4(a, Ab + k16 * 32);
            #pragma unroll
            for (int j2 = 0; j2 < 2; j2++)
                ldsm4(b[j2], Bb + j2 * 16 * 144 + k16 * 32);
            #pragma unroll
            for (int jd = 0; jd < 4; jd++)
                mma16816(c[jd], a, b[jd >> 1] + (jd & 1) * 2);
        }
    }

    // reduce column sums S[n] over the 8 b-groups
    s_part[t] = s_local;
    __syncthreads();
    if (t < 32) {
        float s = 0.0f;
        #pragma unroll
        for (int g = 0; g < 8; g++) s += s_part[t + 32 * g];
        s_sm[t] = s;
    }
    __syncthreads();

    const float invB = 1.0f / (float)BATCH;
    #pragma unroll
    for (int h = 0; h < 2; h++) {
        int nl = wn * 16 + h * 8 + (lane >> 2);
        int n = n0 + nl;
        float s = s_sm[nl];
        #pragma unroll
        for (int jd = 0; jd < 4; jd++) {
            int d = d0 + wd * 32 + jd * 8 + 2 * (lane & 3);
            size_t idx = (size_t)n * FEATS + d;
            float2 wv = *(const float2*)&w[idx];
            float a0 = c[jd][2 * h], a1 = c[jd][2 * h + 1];
            float2 o;
            o.x = wv.x + (a0 - s * wv.x) * invB;
            o.y = wv.y + (a1 - s * wv.y) * invB;
            *(float2*)&out[idx] = o;
        }
    }

    // emit bmu indices (as float) after the map if there is room
    if (bx < 4 && out_size >= NODES * FEATS + BATCH) {
        int b = bx * 256 + t;
        out[NODES * FEATS + b] =
            (float)(unsigned)(g_best[b] & 0xFFFFFFFFull);
    }
}

// ============================================================
extern "C" void kernel_launch(void* const* d_in, const int* in_sizes, int n_in,
                              void* d_out, int out_size) {
    const float* x = nullptr;
    const float* w = nullptr;
    const int* iter = nullptr;
    for (int i = 0; i < n_in; i++) {
        if (in_sizes[i] == BATCH * FEATS)      x = (const float*)d_in[i];
        else if (in_sizes[i] == NODES * FEATS) w = (const float*)d_in[i];
        else if (in_sizes[i] == 1)             iter = (const int*)d_in[i];
    }
    float* out = (float*)d_out;

    cudaFuncSetAttribute(k_bmu, cudaFuncAttributeMaxDynamicSharedMemorySize, SM_BMU);

    k_prep_all<<<704, 256>>>(x, w, iter);
    dim3 gb(NODES / 128, BATCH / 128);
    k_bmu<<<gb, 256, SM_BMU>>>();
    k_update<<<(NODES / 32) * (FEATS / 128), 256>>>(w, out, out_size);
}

// round 15
// speedup vs baseline: 1.1582x; 1.1582x over previous
#include <cuda_runtime.h>
#include <cuda_fp16.h>
#include <stdint.h>

// ---- SOM constants (match reference) ----
#define NODES 4096
#define FEATS 256
#define BATCH 1024
#define SIGMA_F 70.4f        // max(M,N) * 1.1
#define TOTAL_ITER_F 100000.0f

typedef unsigned long long u64;

// ---- device scratch (no allocations allowed) ----
__device__ u64   g_best[BATCH];
__device__ float g_w2[NODES];
__device__ float g_params[3];   // [0]=lr, [1]=1/(2 r^2), [2]=r^2
__device__ __align__(16) __half g_xh[BATCH * FEATS];
__device__ __align__(16) __half g_xl[BATCH * FEATS];
__device__ __align__(16) __half g_wh[NODES * FEATS];
__device__ __align__(16) __half g_wl[NODES * FEATS];
__device__ __align__(16) __half g_xt[FEATS * BATCH];   // x transposed, fp16

// ---- PTX helpers ----
__device__ __forceinline__ uint32_t smem_u32(const void* p) {
    uint32_t a;
    asm("{ .reg .u64 t; cvta.to.shared.u64 t, %1; cvt.u32.u64 %0, t; }"
        : "=r"(a) : "l"(p));
    return a;
}
__device__ __forceinline__ void cp16(uint32_t dst, const void* src) {
    asm volatile("cp.async.cg.shared.global [%0], [%1], 16;"
                 :: "r"(dst), "l"(src));
}
#define CP_COMMIT() asm volatile("cp.async.commit_group;" ::: "memory")
#define CP_WAIT0()  asm volatile("cp.async.wait_group 0;" ::: "memory")

__device__ __forceinline__ void ldsm4(uint32_t* r, uint32_t addr) {
    asm volatile("ldmatrix.sync.aligned.m8n8.x4.shared.b16 {%0,%1,%2,%3}, [%4];"
                 : "=r"(r[0]), "=r"(r[1]), "=r"(r[2]), "=r"(r[3]) : "r"(addr));
}
__device__ __forceinline__ void mma16816(float* c, const uint32_t* a,
                                         const uint32_t* b) {
    asm volatile(
        "mma.sync.aligned.m16n8k16.row.col.f32.f16.f16.f32 "
        "{%0,%1,%2,%3}, {%4,%5,%6,%7}, {%8,%9}, {%0,%1,%2,%3};"
        : "+f"(c[0]), "+f"(c[1]), "+f"(c[2]), "+f"(c[3])
        : "r"(a[0]), "r"(a[1]), "r"(a[2]), "r"(a[3]), "r"(b[0]), "r"(b[1]));
}
__device__ __forceinline__ u64 packkey(float d, int n) {
    unsigned u = __float_as_uint(d);
    u = (u & 0x80000000u) ? ~u : (u | 0x80000000u);
    return ((u64)u << 32) | (unsigned)n;
}

// ============================================================
// K1: fused prep (grid-704 layout, proven 6.3us).
// ============================================================
__device__ __forceinline__ void split8(const float* src, __half* hi, __half* lo,
                                       float* sumsq) {
    float4 va = ((const float4*)src)[0];
    float4 vb = ((const float4*)src)[1];
    float f[8] = {va.x, va.y, va.z, va.w, vb.x, vb.y, vb.z, vb.w};
    __half2 h2[4], l2[4];
    float s = 0.0f;
    #pragma unroll
    for (int i = 0; i < 4; i++) {
        float a = f[2 * i], b = f[2 * i + 1];
        s += a * a + b * b;
        float ha = __half2float(__float2half_rn(a));
        float hb = __half2float(__float2half_rn(b));
        h2[i] = __floats2half2_rn(ha, hb);
        l2[i] = __floats2half2_rn(a - ha, b - hb);
    }
    *(uint4*)hi = *(uint4*)h2;
    *(uint4*)lo = *(uint4*)l2;
    if (sumsq) *sumsq = s;
}

__global__ void __launch_bounds__(256) k_prep_all(const float* __restrict__ x,
                                                  const float* __restrict__ w,
                                                  const int* __restrict__ iter) {
    int bid = blockIdx.x;
    int t = threadIdx.x;
    int warp = t >> 5, lane = t & 31;

    if (bid < 512) {                       // w rows: split + w2
        int n = bid * 8 + warp;
        int c = lane * 8;
        float s;
        split8(w + (size_t)n * FEATS + c, g_wh + n * FEATS + c,
               g_wl + n * FEATS + c, &s);
        #pragma unroll
        for (int o = 16; o; o >>= 1) s += __shfl_xor_sync(0xFFFFFFFFu, s, o);
        if (lane == 0) g_w2[n] = s;
    } else if (bid < 640) {                // x rows: split
        int r = (bid - 512) * 8 + warp;
        int c = lane * 8;
        split8(x + (size_t)r * FEATS + c, g_xh + r * FEATS + c,
               g_xl + r * FEATS + c, nullptr);
    } else {                               // x transpose tiles
        __shared__ float s[64][65];
        int bx2 = bid - 640;
        if (bx2 < 4) {
            g_best[bx2 * 256 + t] = 0xFFFFFFFFFFFFFFFFull;
            if (bx2 == 0 && t == 0) {
                float lambda_g = TOTAL_ITER_F / SIGMA_F;
                float decay    = expf(-(float)iter[0] / lambda_g);
                float radius   = SIGMA_F * decay + 1e-6f;
                g_params[0] = 0.5f * decay;
                g_params[1] = 1.0f / (2.0f * radius * radius);
                g_params[2] = radius * radius;
            }
        }
        int b0 = (bx2 >> 2) * 64, d0 = (bx2 & 3) * 64;
        #pragma unroll
        for (int q = 0; q < 16; q++) {
            int e = q * 256 + t;
            int br = e >> 6, dc = e & 63;
            s[br][dc] = x[(size_t)(b0 + br) * FEATS + d0 + dc];
        }
        __syncthreads();
        #pragma unroll
        for (int q = 0; q < 16; q++) {
            int e = q * 256 + t;
            int dr = e >> 6, bc = e & 63;
            g_xt[(size_t)(d0 + dr) * BATCH + b0 + bc] = __float2half_rn(s[bc][dr]);
        }
    }
}

// ============================================================
// K2: BMU GEMM via HMMA (proven, unchanged).
// ============================================================
#define ASZ (128 * 144)
#define BSZ (128 * 144)
#define OFF_A 1024
#define OFF_B (1024 + 2 * ASZ)
#define SM_BMU (OFF_B + 2 * BSZ)

__device__ __forceinline__ void stage_bmu(uint32_t sb, int buf, int ch,
                                          int m0, int n0, int t) {
    int term = ch >> 2;
    int kk = (ch & 3) * 64;
    const __half* asrc = (term < 2) ? g_xh : g_xl;
    const __half* bsrc = (term == 1) ? g_wl : g_wh;
    uint32_t adst = sb + OFF_A + buf * ASZ;
    uint32_t bdst = sb + OFF_B + buf * BSZ;
    #pragma unroll
    for (int q = 0; q < 4; q++) {
        int g = t + 256 * q; int r = g >> 3, c = g & 7;
        cp16(adst + r * 144 + c * 16, asrc + (size_t)(m0 + r) * FEATS + kk + c * 8);
        cp16(bdst + r * 144 + c * 16, bsrc + (size_t)(n0 + r) * FEATS + kk + c * 8);
    }
    CP_COMMIT();
}

__global__ void __launch_bounds__(256, 2) k_bmu() {
    extern __shared__ char sm[];
    uint32_t sb = smem_u32(sm);
    float* w2s = (float*)sm;
    int t = threadIdx.x, lane = t & 31, warp = t >> 5;
    int wm = warp >> 1, wn = warp & 1;     // 4m x 2n warp grid
    int n0 = blockIdx.x * 128;
    int m0 = blockIdx.y * 128;

    if (t < 128) w2s[t] = g_w2[n0 + t];

    float c[2][8][4];
    #pragma unroll
    for (int i = 0; i < 2; i++)
        #pragma unroll
        for (int j = 0; j < 8; j++)
            #pragma unroll
            for (int q = 0; q < 4; q++) c[i][j][q] = 0.0f;

    uint32_t aoff = (uint32_t)((lane & 15) * 144 + (lane >> 4) * 16);
    uint32_t boff = (uint32_t)(((lane & 7) + ((lane >> 4) << 3)) * 144
                               + (((lane >> 3) & 1) << 4));

    stage_bmu(sb, 0, 0, m0, n0, t);
    for (int ch = 0; ch < 12; ch++) {
        CP_WAIT0();
        __syncthreads();   // data visible + prior-iter reads of buf^1 done
        if (ch + 1 < 12) stage_bmu(sb, (ch + 1) & 1, ch + 1, m0, n0, t);

        uint32_t Ab = sb + OFF_A + (ch & 1) * ASZ + (wm * 32) * 144 + aoff;
        uint32_t Bb = sb + OFF_B + (ch & 1) * BSZ + (wn * 64) * 144 + boff;
        #pragma unroll
        for (int k16 = 0; k16 < 4; k16++) {
            uint32_t a[2][4], b[4][4];
            #pragma unroll
            for (int im = 0; im < 2; im++)
                ldsm4(a[im], Ab + im * 16 * 144 + k16 * 32);
            #pragma unroll
            for (int j2 = 0; j2 < 4; j2++)
                ldsm4(b[j2], Bb + j2 * 16 * 144 + k16 * 32);
            #pragma unroll
            for (int im = 0; im < 2; im++)
                #pragma unroll
                for (int j2 = 0; j2 < 4; j2++) {
                    mma16816(c[im][2 * j2],     a[im], b[j2]);
                    mma16816(c[im][2 * j2 + 1], a[im], b[j2] + 2);
                }
        }
    }

    // fused argmin epilogue
    #pragma unroll
    for (int im = 0; im < 2; im++) {
        #pragma unroll
        for (int h = 0; h < 2; h++) {
            float best = __int_as_float(0x7F800000);
            int bestn = 0;
            #pragma unroll
            for (int j8 = 0; j8 < 8; j8++) {
                int nl = wn * 64 + j8 * 8 + 2 * (lane & 3);
                float v0 = w2s[nl]     - 2.0f * c[im][j8][2 * h];
                float v1 = w2s[nl + 1] - 2.0f * c[im][j8][2 * h + 1];
                if (v0 < best) { best = v0; bestn = nl; }
                if (v1 < best) { best = v1; bestn = nl + 1; }
            }
            #pragma unroll
            for (int o = 1; o <= 2; o <<= 1) {
                float od = __shfl_xor_sync(0xFFFFFFFFu, best, o);
                int   on = __shfl_xor_sync(0xFFFFFFFFu, bestn, o);
                if (od < best || (od == best && on < bestn)) { best = od; bestn = on; }
            }
            if ((lane & 3) == 0) {
                int m = m0 + wm * 32 + im * 16 + h * 8 + (lane >> 2);
                atomicMin(&g_best[m], packkey(best, n0 + bestn));
            }
        }
    }
}

// ============================================================
// K3: update GEMM (R7 champion structure, byte-identical schedule:
// 32n x 128d, grid 256, 2 CTAs/SM, gen-AHEAD L overlapped with
// compute, 2-stage X pipe, one sync/chunk).
// ONE delta vs R7: gen_L uses a CONTIGUOUS b-slice per thread ->
// 4x LDG.128 (g_best pairs) + 1x STS.128 (packed half2 x4) instead
// of 8x LDG.64 + 8x scalar STS. __expf kept (MUFU pipe is idle).
// ============================================================
__global__ void __launch_bounds__(256, 2) k_update(const float* __restrict__ w,
                                                   float* __restrict__ out,
                                                   int out_size) {
    __shared__ float s_sm[32];
    __shared__ float s_part[256];
    __shared__ __align__(16) __half Ls[2][32 * 72];
    __shared__ __align__(16) __half Xs[2][128 * 72];

    uint32_t sbL = smem_u32(Ls);
    uint32_t sbX = smem_u32(Xs);

    int t = threadIdx.x, lane = t & 31, warp = t >> 5;
    int wn = warp >> 2, wd = warp & 3;     // 2n x 4d warp grid
    int bx = blockIdx.x;
    int n0 = (bx >> 1) * 32;
    int d0 = (bx & 1) * 128;

    float lr = g_params[0], inv2r2 = g_params[1], r2 = g_params[2];

    int n_l = t & 31;
    int gn = n0 + n_l;
    int ni = gn >> 6, nj = gn & 63;
    int bgrp = t >> 5;          // 0..7 -> contiguous b-slice [bgrp*8, bgrp*8+8)
    float s_local = 0.0f;

    float c[4][4];
    #pragma unroll
    for (int j = 0; j < 4; j++)
        #pragma unroll
        for (int q = 0; q < 4; q++) c[j][q] = 0.0f;

    uint32_t aoff = (uint32_t)((lane & 15) * 144 + (lane >> 4) * 16);
    uint32_t boff = (uint32_t)(((lane & 7) + ((lane >> 4) << 3)) * 144
                               + (((lane >> 3) & 1) << 4));

    // L generator: thread n = t&31, b in [ch*64 + bgrp*8, +8) contiguous.
    // 4x uint4 loads (2 packed argmin keys each; bmu = low u32), compute 8
    // neighborhood values via __expf, pack to 4 half2, 1x uint4 store.
    auto gen_L = [&](int ch, int buf) {
        const uint4* gp = (const uint4*)&g_best[ch * 64 + bgrp * 8];
        uint4 q0 = gp[0], q1 = gp[1], q2 = gp[2], q3 = gp[3];
        unsigned bm[8] = {q0.x, q0.z, q1.x, q1.z, q2.x, q2.z, q3.x, q3.z};
        __half2 hv[4];
        #pragma unroll
        for (int e = 0; e < 4; e++) {
            int b0 = (int)bm[2 * e], b1 = (int)bm[2 * e + 1];
            float di0 = (float)(ni - (b0 >> 6)), dj0 = (float)(nj - (b0 & 63));
            float di1 = (float)(ni - (b1 >> 6)), dj1 = (float)(nj - (b1 & 63));
            float d20 = di0 * di0 + dj0 * dj0;
            float d21 = di1 * di1 + dj1 * dj1;
            float v0 = (d20 <= r2) ? lr * __expf(-d20 * inv2r2) : 0.0f;
            float v1 = (d21 <= r2) ? lr * __expf(-d21 * inv2r2) : 0.0f;
            s_local += v0 + v1;
            hv[e] = __floats2half2_rn(v0, v1);
        }
        *(uint4*)&Ls[buf][n_l * 72 + bgrp * 8] = *(uint4*)hv;
    };

    // prologue: stage X(0), generate L(0)
    #pragma unroll
    for (int q = 0; q < 4; q++) {
        int g = t + 256 * q; int r = g >> 3, cc = g & 7;
        cp16(sbX + r * 144 + cc * 16, g_xt + (size_t)(d0 + r) * BATCH + cc * 8);
    }
    CP_COMMIT();
    gen_L(0, 0);

    for (int ch = 0; ch < 16; ch++) {
        CP_WAIT0();
        __syncthreads();   // X(ch)+L(ch) visible; prior reads of buf^1 done
        if (ch + 1 < 16) {
            uint32_t xdst = sbX + ((ch + 1) & 1) * (128 * 144);
            #pragma unroll
            for (int q = 0; q < 4; q++) {
                int g = t + 256 * q; int r = g >> 3, cc = g & 7;
                cp16(xdst + r * 144 + cc * 16,
                     g_xt + (size_t)(d0 + r) * BATCH + (ch + 1) * 64 + cc * 8);
            }
            CP_COMMIT();
            gen_L(ch + 1, (ch + 1) & 1);   // overlapped with compute below
        }

        uint32_t Ab = sbL + (ch & 1) * (32 * 144) + (wn * 16) * 144 + aoff;
        uint32_t Bb = sbX + (ch & 1) * (128 * 144) + (wd * 32) * 144 + boff;
        #pragma unroll
        for (int k16 = 0; k16 < 4; k16++) {
            uint32_t a[4], b[2][4];
            ldsm4(a, Ab + k16 * 32);
            #pragma unroll
            for (int j2 = 0; j2 < 2; j2++)
                ldsm4(b[j2], Bb + j2 * 16 * 144 + k16 * 32);
            #pragma unroll
            for (int jd = 0; jd < 4; jd++)
                mma16816(c[jd], a, b[jd >> 1] + (jd & 1) * 2);
        }
    }

    // reduce column sums S[n] over the 8 b-groups
    s_part[t] = s_local;
    __syncthreads();
    if (t < 32) {
        float s = 0.0f;
        #pragma unroll
        for (int g = 0; g < 8; g++) s += s_part[t + 32 * g];
        s_sm[t] = s;
    }
    __syncthreads();

    const float invB = 1.0f / (float)BATCH;
    #pragma unroll
    for (int h = 0; h < 2; h++) {
        int nl = wn * 16 + h * 8 + (lane >> 2);
        int n = n0 + nl;
        float s = s_sm[nl];
        #pragma unroll
        for (int jd = 0; jd < 4; jd++) {
            int d = d0 + wd * 32 + jd * 8 + 2 * (lane & 3);
            size_t idx = (size_t)n * FEATS + d;
            float2 wv = *(const float2*)&w[idx];
            float a0 = c[jd][2 * h], a1 = c[jd][2 * h + 1];
            float2 o;
            o.x = wv.x + (a0 - s * wv.x) * invB;
            o.y = wv.y + (a1 - s * wv.y) * invB;
            *(float2*)&out[idx] = o;
        }
    }

    // emit bmu indices (as float) after the map if there is room
    if (bx < 4 && out_size >= NODES * FEATS + BATCH) {
        int b = bx * 256 + t;
        out[NODES * FEATS + b] =
            (float)(unsigned)(g_best[b] & 0xFFFFFFFFull);
    }
}

// ============================================================
extern "C" void kernel_launch(void* const* d_in, const int* in_sizes, int n_in,
                              void* d_out, int out_size) {
    const float* x = nullptr;
    const float* w = nullptr;
    const int* iter = nullptr;
    for (int i = 0; i < n_in; i++) {
        if (in_sizes[i] == BATCH * FEATS)      x = (const float*)d_in[i];
        else if (in_sizes[i] == NODES * FEATS) w = (const float*)d_in[i];
        else if (in_sizes[i] == 1)             iter = (const int*)d_in[i];
    }
    float* out = (float*)d_out;

    cudaFuncSetAttribute(k_bmu, cudaFuncAttributeMaxDynamicSharedMemorySize, SM_BMU);

    k_prep_all<<<704, 256>>>(x, w, iter);
    dim3 gb(NODES / 128, BATCH / 128);
    k_bmu<<<gb, 256, SM_BMU>>>();
    k_update<<<(NODES / 32) * (FEATS / 128), 256>>>(w, out, out_size);
}

// round 16
// speedup vs baseline: 1.1597x; 1.0013x over previous
#include <cuda_runtime.h>
#include <cuda_fp16.h>
#include <stdint.h>

// ---- SOM constants (match reference) ----
#define NODES 4096
#define FEATS 256
#define BATCH 1024
#define SIGMA_F 70.4f        // max(M,N) * 1.1
#define TOTAL_ITER_F 100000.0f

typedef unsigned long long u64;

// ---- device scratch (no allocations allowed) ----
__device__ u64   g_best[BATCH];
__device__ float g_w2[NODES];
__device__ float g_params[3];   // [0]=lr, [1]=1/(2 r^2), [2]=r^2
__device__ __align__(16) __half g_xh[BATCH * FEATS];
__device__ __align__(16) __half g_xl[BATCH * FEATS];
__device__ __align__(16) __half g_wh[NODES * FEATS];
__device__ __align__(16) __half g_wl[NODES * FEATS];
__device__ __align__(16) __half g_xt[FEATS * BATCH];   // x transposed, fp16

// ---- PTX helpers ----
__device__ __forceinline__ uint32_t smem_u32(const void* p) {
    uint32_t a;
    asm("{ .reg .u64 t; cvta.to.shared.u64 t, %1; cvt.u32.u64 %0, t; }"
        : "=r"(a) : "l"(p));
    return a;
}
__device__ __forceinline__ void cp16(uint32_t dst, const void* src) {
    asm volatile("cp.async.cg.shared.global [%0], [%1], 16;"
                 :: "r"(dst), "l"(src));
}
#define CP_COMMIT() asm volatile("cp.async.commit_group;" ::: "memory")
#define CP_WAIT0()  asm volatile("cp.async.wait_group 0;" ::: "memory")

__device__ __forceinline__ void ldsm4(uint32_t* r, uint32_t addr) {
    asm volatile("ldmatrix.sync.aligned.m8n8.x4.shared.b16 {%0,%1,%2,%3}, [%4];"
                 : "=r"(r[0]), "=r"(r[1]), "=r"(r[2]), "=r"(r[3]) : "r"(addr));
}
__device__ __forceinline__ void mma16816(float* c, const uint32_t* a,
                                         const uint32_t* b) {
    asm volatile(
        "mma.sync.aligned.m16n8k16.row.col.f32.f16.f16.f32 "
        "{%0,%1,%2,%3}, {%4,%5,%6,%7}, {%8,%9}, {%0,%1,%2,%3};"
        : "+f"(c[0]), "+f"(c[1]), "+f"(c[2]), "+f"(c[3])
        : "r"(a[0]), "r"(a[1]), "r"(a[2]), "r"(a[3]), "r"(b[0]), "r"(b[1]));
}
__device__ __forceinline__ u64 packkey(float d, int n) {
    unsigned u = __float_as_uint(d);
    u = (u & 0x80000000u) ? ~u : (u | 0x80000000u);
    return ((u64)u << 32) | (unsigned)n;
}

// ============================================================
// K1: fused prep (grid-704 layout, proven).
// ============================================================
__device__ __forceinline__ void split8(const float* src, __half* hi, __half* lo,
                                       float* sumsq) {
    float4 va = ((const float4*)src)[0];
    float4 vb = ((const float4*)src)[1];
    float f[8] = {va.x, va.y, va.z, va.w, vb.x, vb.y, vb.z, vb.w};
    __half2 h2[4], l2[4];
    float s = 0.0f;
    #pragma unroll
    for (int i = 0; i < 4; i++) {
        float a = f[2 * i], b = f[2 * i + 1];
        s += a * a + b * b;
        float ha = __half2float(__float2half_rn(a));
        float hb = __half2float(__float2half_rn(b));
        h2[i] = __floats2half2_rn(ha, hb);
        l2[i] = __floats2half2_rn(a - ha, b - hb);
    }
    *(uint4*)hi = *(uint4*)h2;
    *(uint4*)lo = *(uint4*)l2;
    if (sumsq) *sumsq = s;
}

__global__ void __launch_bounds__(256) k_prep_all(const float* __restrict__ x,
                                                  const float* __restrict__ w,
                                                  const int* __restrict__ iter) {
    int bid = blockIdx.x;
    int t = threadIdx.x;
    int warp = t >> 5, lane = t & 31;

    if (bid < 512) {                       // w rows: split + w2
        int n = bid * 8 + warp;
        int c = lane * 8;
        float s;
        split8(w + (size_t)n * FEATS + c, g_wh + n * FEATS + c,
               g_wl + n * FEATS + c, &s);
        #pragma unroll
        for (int o = 16; o; o >>= 1) s += __shfl_xor_sync(0xFFFFFFFFu, s, o);
        if (lane == 0) g_w2[n] = s;
    } else if (bid < 640) {                // x rows: split
        int r = (bid - 512) * 8 + warp;
        int c = lane * 8;
        split8(x + (size_t)r * FEATS + c, g_xh + r * FEATS + c,
               g_xl + r * FEATS + c, nullptr);
    } else {                               // x transpose tiles
        __shared__ float s[64][65];
        int bx2 = bid - 640;
        if (bx2 < 4) {
            g_best[bx2 * 256 + t] = 0xFFFFFFFFFFFFFFFFull;
            if (bx2 == 0 && t == 0) {
                float lambda_g = TOTAL_ITER_F / SIGMA_F;
                float decay    = expf(-(float)iter[0] / lambda_g);
                float radius   = SIGMA_F * decay + 1e-6f;
                g_params[0] = 0.5f * decay;
                g_params[1] = 1.0f / (2.0f * radius * radius);
                g_params[2] = radius * radius;
            }
        }
        int b0 = (bx2 >> 2) * 64, d0 = (bx2 & 3) * 64;
        #pragma unroll
        for (int q = 0; q < 16; q++) {
            int e = q * 256 + t;
            int br = e >> 6, dc = e & 63;
            s[br][dc] = x[(size_t)(b0 + br) * FEATS + d0 + dc];
        }
        __syncthreads();
        #pragma unroll
        for (int q = 0; q < 16; q++) {
            int e = q * 256 + t;
            int dr = e >> 6, bc = e & 63;
            g_xt[(size_t)(d0 + dr) * BATCH + b0 + bc] = __float2half_rn(s[bc][dr]);
        }
    }
}

// ============================================================
// K2: BMU GEMM via HMMA (proven, unchanged).
// ============================================================
#define ASZ (128 * 144)
#define BSZ (128 * 144)
#define OFF_A 1024
#define OFF_B (1024 + 2 * ASZ)
#define SM_BMU (OFF_B + 2 * BSZ)

__device__ __forceinline__ void stage_bmu(uint32_t sb, int buf, int ch,
                                          int m0, int n0, int t) {
    int term = ch >> 2;
    int kk = (ch & 3) * 64;
    const __half* asrc = (term < 2) ? g_xh : g_xl;
    const __half* bsrc = (term == 1) ? g_wl : g_wh;
    uint32_t adst = sb + OFF_A + buf * ASZ;
    uint32_t bdst = sb + OFF_B + buf * BSZ;
    #pragma unroll
    for (int q = 0; q < 4; q++) {
        int g = t + 256 * q; int r = g >> 3, c = g & 7;
        cp16(adst + r * 144 + c * 16, asrc + (size_t)(m0 + r) * FEATS + kk + c * 8);
        cp16(bdst + r * 144 + c * 16, bsrc + (size_t)(n0 + r) * FEATS + kk + c * 8);
    }
    CP_COMMIT();
}

__global__ void __launch_bounds__(256, 2) k_bmu() {
    extern __shared__ char sm[];
    uint32_t sb = smem_u32(sm);
    float* w2s = (float*)sm;
    int t = threadIdx.x, lane = t & 31, warp = t >> 5;
    int wm = warp >> 1, wn = warp & 1;     // 4m x 2n warp grid
    int n0 = blockIdx.x * 128;
    int m0 = blockIdx.y * 128;

    if (t < 128) w2s[t] = g_w2[n0 + t];

    float c[2][8][4];
    #pragma unroll
    for (int i = 0; i < 2; i++)
        #pragma unroll
        for (int j = 0; j < 8; j++)
            #pragma unroll
            for (int q = 0; q < 4; q++) c[i][j][q] = 0.0f;

    uint32_t aoff = (uint32_t)((lane & 15) * 144 + (lane >> 4) * 16);
    uint32_t boff = (uint32_t)(((lane & 7) + ((lane >> 4) << 3)) * 144
                               + (((lane >> 3) & 1) << 4));

    stage_bmu(sb, 0, 0, m0, n0, t);
    for (int ch = 0; ch < 12; ch++) {
        CP_WAIT0();
        __syncthreads();
        if (ch + 1 < 12) stage_bmu(sb, (ch + 1) & 1, ch + 1, m0, n0, t);

        uint32_t Ab = sb + OFF_A + (ch & 1) * ASZ + (wm * 32) * 144 + aoff;
        uint32_t Bb = sb + OFF_B + (ch & 1) * BSZ + (wn * 64) * 144 + boff;
        #pragma unroll
        for (int k16 = 0; k16 < 4; k16++) {
            uint32_t a[2][4], b[4][4];
            #pragma unroll
            for (int im = 0; im < 2; im++)
                ldsm4(a[im], Ab + im * 16 * 144 + k16 * 32);
            #pragma unroll
            for (int j2 = 0; j2 < 4; j2++)
                ldsm4(b[j2], Bb + j2 * 16 * 144 + k16 * 32);
            #pragma unroll
            for (int im = 0; im < 2; im++)
                #pragma unroll
                for (int j2 = 0; j2 < 4; j2++) {
                    mma16816(c[im][2 * j2],     a[im], b[j2]);
                    mma16816(c[im][2 * j2 + 1], a[im], b[j2] + 2);
                }
        }
    }

    #pragma unroll
    for (int im = 0; im < 2; im++) {
        #pragma unroll
        for (int h = 0; h < 2; h++) {
            float best = __int_as_float(0x7F800000);
            int bestn = 0;
            #pragma unroll
            for (int j8 = 0; j8 < 8; j8++) {
                int nl = wn * 64 + j8 * 8 + 2 * (lane & 3);
                float v0 = w2s[nl]     - 2.0f * c[im][j8][2 * h];
                float v1 = w2s[nl + 1] - 2.0f * c[im][j8][2 * h + 1];
                if (v0 < best) { best = v0; bestn = nl; }
                if (v1 < best) { best = v1; bestn = nl + 1; }
            }
            #pragma unroll
            for (int o = 1; o <= 2; o <<= 1) {
                float od = __shfl_xor_sync(0xFFFFFFFFu, best, o);
                int   on = __shfl_xor_sync(0xFFFFFFFFu, bestn, o);
                if (od < best || (od == best && on < bestn)) { best = od; bestn = on; }
            }
            if ((lane & 3) == 0) {
                int m = m0 + wm * 32 + im * 16 + h * 8 + (lane >> 2);
                atomicMin(&g_best[m], packkey(best, n0 + bestn));
            }
        }
    }
}

// ============================================================
// K3: update GEMM. Champion schedule (gen-AHEAD overlapped, one
// sync/chunk, vectorized gen_L), ONE delta: 128-b chunks -> 8
// chunks instead of 16 (half the barriers, 2x compute/barrier).
// Row stride 272B (256B row + 16B skew). Dynamic smem ~88KB,
// still 2 CTAs/SM (228KB smem/SM).
// ============================================================
#define UXSZ (128 * 272)              // one X stage: 128 d-rows x 128 b
#define ULSZ (32 * 272)               // one L stage: 32 n-rows x 128 b
#define UOFF_X 0
#define UOFF_L (2 * UXSZ)             // 69632
#define UOFF_SP (UOFF_L + 2 * ULSZ)   // 87040
#define UOFF_SS (UOFF_SP + 1024)      // 88064
#define SM_UPD (UOFF_SS + 128)        // 88192

__global__ void __launch_bounds__(256, 2) k_update(const float* __restrict__ w,
                                                   float* __restrict__ out,
                                                   int out_size) {
    extern __shared__ char sm[];
    uint32_t sb = smem_u32(sm);
    float* s_part = (float*)(sm + UOFF_SP);
    float* s_sm   = (float*)(sm + UOFF_SS);

    int t = threadIdx.x, lane = t & 31, warp = t >> 5;
    int wn = warp >> 2, wd = warp & 3;     // 2n x 4d warp grid
    int bx = blockIdx.x;
    int n0 = (bx >> 1) * 32;
    int d0 = (bx & 1) * 128;

    float lr = g_params[0], inv2r2 = g_params[1], r2 = g_params[2];

    int n_l = t & 31;
    int gn = n0 + n_l;
    int ni = gn >> 6, nj = gn & 63;
    int bgrp = t >> 5;          // 0..7 -> contiguous b-slice [bgrp*16, +16)
    float s_local = 0.0f;

    float c[4][4];
    #pragma unroll
    for (int j = 0; j < 4; j++)
        #pragma unroll
        for (int q = 0; q < 4; q++) c[j][q] = 0.0f;

    uint32_t aoff = (uint32_t)((lane & 15) * 272 + (lane >> 4) * 16);
    uint32_t boff = (uint32_t)(((lane & 7) + ((lane >> 4) << 3)) * 272
                               + (((lane >> 3) & 1) << 4));

    // L generator: thread n = t&31, b in [ch*128 + bgrp*16, +16) contiguous.
    // 8x LDG.128 (argmin-key pairs), 16 __expf values, 2x STS.128.
    auto gen_L = [&](int ch, int buf) {
        __half* Lrow = (__half*)(sm + UOFF_L + buf * ULSZ) + n_l * 136 + bgrp * 16;
        const uint4* gp = (const uint4*)&g_best[ch * 128 + bgrp * 16];
        __half2 hv[8];
        #pragma unroll
        for (int e = 0; e < 8; e++) {
            uint4 qq = gp[e];
            int b0 = (int)qq.x, b1 = (int)qq.z;
            float di0 = (float)(ni - (b0 >> 6)), dj0 = (float)(nj - (b0 & 63));
            float di1 = (float)(ni - (b1 >> 6)), dj1 = (float)(nj - (b1 & 63));
            float d20 = di0 * di0 + dj0 * dj0;
            float d21 = di1 * di1 + dj1 * dj1;
            float v0 = (d20 <= r2) ? lr * __expf(-d20 * inv2r2) : 0.0f;
            float v1 = (d21 <= r2) ? lr * __expf(-d21 * inv2r2) : 0.0f;
            s_local += v0 + v1;
            hv[e] = __floats2half2_rn(v0, v1);
        }
        ((uint4*)Lrow)[0] = ((uint4*)hv)[0];
        ((uint4*)Lrow)[1] = ((uint4*)hv)[1];
    };

    auto stage_x = [&](int ch, int buf) {
        uint32_t xdst = sb + UOFF_X + buf * UXSZ;
        #pragma unroll
        for (int q = 0; q < 8; q++) {
            int g = t + 256 * q; int r = g >> 4, cc = g & 15;
            cp16(xdst + r * 272 + cc * 16,
                 g_xt + (size_t)(d0 + r) * BATCH + ch * 128 + cc * 8);
        }
        CP_COMMIT();
    };

    // prologue: stage X(0), generate L(0)
    stage_x(0, 0);
    gen_L(0, 0);

    for (int ch = 0; ch < 8; ch++) {
        CP_WAIT0();
        __syncthreads();   // X(ch)+L(ch) visible; prior reads of buf^1 done
        if (ch + 1 < 8) {
            stage_x(ch + 1, (ch + 1) & 1);
            gen_L(ch + 1, (ch + 1) & 1);   // overlapped with compute below
        }

        uint32_t Ab = sb + UOFF_L + (ch & 1) * ULSZ + (wn * 16) * 272 + aoff;
        uint32_t Bb = sb + UOFF_X + (ch & 1) * UXSZ + (wd * 32) * 272 + boff;
        #pragma unroll
        for (int k16 = 0; k16 < 8; k16++) {
            uint32_t a[4], b[2][4];
            ldsm4(a, Ab + k16 * 32);
            #pragma unroll
            for (int j2 = 0; j2 < 2; j2++)
                ldsm4(b[j2], Bb + j2 * 16 * 272 + k16 * 32);
            #pragma unroll
            for (int jd = 0; jd < 4; jd++)
                mma16816(c[jd], a, b[jd >> 1] + (jd & 1) * 2);
        }
    }

    // reduce column sums S[n] over the 8 b-groups
    s_part[t] = s_local;
    __syncthreads();
    if (t < 32) {
        float s = 0.0f;
        #pragma unroll
        for (int g = 0; g < 8; g++) s += s_part[t + 32 * g];
        s_sm[t] = s;
    }
    __syncthreads();

    const float invB = 1.0f / (float)BATCH;
    #pragma unroll
    for (int h = 0; h < 2; h++) {
        int nl = wn * 16 + h * 8 + (lane >> 2);
        int n = n0 + nl;
        float s = s_sm[nl];
        #pragma unroll
        for (int jd = 0; jd < 4; jd++) {
            int d = d0 + wd * 32 + jd * 8 + 2 * (lane & 3);
            size_t idx = (size_t)n * FEATS + d;
            float2 wv = *(const float2*)&w[idx];
            float a0 = c[jd][2 * h], a1 = c[jd][2 * h + 1];
            float2 o;
            o.x = wv.x + (a0 - s * wv.x) * invB;
            o.y = wv.y + (a1 - s * wv.y) * invB;
            *(float2*)&out[idx] = o;
        }
    }

    // emit bmu indices (as float) after the map if there is room
    if (bx < 4 && out_size >= NODES * FEATS + BATCH) {
        int b = bx * 256 + t;
        out[NODES * FEATS + b] =
            (float)(unsigned)(g_best[b] & 0xFFFFFFFFull);
    }
}

// ============================================================
extern "C" void kernel_launch(void* const* d_in, const int* in_sizes, int n_in,
                              void* d_out, int out_size) {
    const float* x = nullptr;
    const float* w = nullptr;
    const int* iter = nullptr;
    for (int i = 0; i < n_in; i++) {
        if (in_sizes[i] == BATCH * FEATS)      x = (const float*)d_in[i];
        else if (in_sizes[i] == NODES * FEATS) w = (const float*)d_in[i];
        else if (in_sizes[i] == 1)             iter = (const int*)d_in[i];
    }
    float* out = (float*)d_out;

    cudaFuncSetAttribute(k_bmu, cudaFuncAttributeMaxDynamicSharedMemorySize, SM_BMU);
    cudaFuncSetAttribute(k_update, cudaFuncAttributeMaxDynamicSharedMemorySize, SM_UPD);

    k_prep_all<<<704, 256>>>(x, w, iter);
    dim3 gb(NODES / 128, BATCH / 128);
    k_bmu<<<gb, 256, SM_BMU>>>();
    k_update<<<(NODES / 32) * (FEATS / 128), 256, SM_UPD>>>(w, out, out_size);
}

// round 17
// speedup vs baseline: 1.1756x; 1.0137x over previous
#include <cuda_runtime.h>
#include <cuda_fp16.h>
#include <stdint.h>

// ---- SOM constants (match reference) ----
#define NODES 4096
#define FEATS 256
#define BATCH 1024
#define SIGMA_F 70.4f        // max(M,N) * 1.1
#define TOTAL_ITER_F 100000.0f

typedef unsigned long long u64;

// ---- device scratch (no allocations allowed) ----
__device__ u64   g_best[BATCH];
__device__ float g_w2[NODES];
__device__ float g_params[3];   // [0]=lr, [1]=1/(2 r^2), [2]=r^2
__device__ __align__(16) __half g_xh[BATCH * FEATS];
__device__ __align__(16) __half g_xl[BATCH * FEATS];
__device__ __align__(16) __half g_wh[NODES * FEATS];
__device__ __align__(16) __half g_wl[NODES * FEATS];
__device__ __align__(16) __half g_xt[FEATS * BATCH];   // x transposed, fp16

// ---- PTX helpers ----
__device__ __forceinline__ uint32_t smem_u32(const void* p) {
    uint32_t a;
    asm("{ .reg .u64 t; cvta.to.shared.u64 t, %1; cvt.u32.u64 %0, t; }"
        : "=r"(a) : "l"(p));
    return a;
}
__device__ __forceinline__ void cp16(uint32_t dst, const void* src) {
    asm volatile("cp.async.cg.shared.global [%0], [%1], 16;"
                 :: "r"(dst), "l"(src));
}
#define CP_COMMIT() asm volatile("cp.async.commit_group;" ::: "memory")
#define CP_WAIT0()  asm volatile("cp.async.wait_group 0;" ::: "memory")

__device__ __forceinline__ void ldsm4(uint32_t* r, uint32_t addr) {
    asm volatile("ldmatrix.sync.aligned.m8n8.x4.shared.b16 {%0,%1,%2,%3}, [%4];"
                 : "=r"(r[0]), "=r"(r[1]), "=r"(r[2]), "=r"(r[3]) : "r"(addr));
}
__device__ __forceinline__ void mma16816(float* c, const uint32_t* a,
                                         const uint32_t* b) {
    asm volatile(
        "mma.sync.aligned.m16n8k16.row.col.f32.f16.f16.f32 "
        "{%0,%1,%2,%3}, {%4,%5,%6,%7}, {%8,%9}, {%0,%1,%2,%3};"
        : "+f"(c[0]), "+f"(c[1]), "+f"(c[2]), "+f"(c[3])
        : "r"(a[0]), "r"(a[1]), "r"(a[2]), "r"(a[3]), "r"(b[0]), "r"(b[1]));
}
__device__ __forceinline__ u64 packkey(float d, int n) {
    unsigned u = __float_as_uint(d);
    u = (u & 0x80000000u) ? ~u : (u | 0x80000000u);
    return ((u64)u << 32) | (unsigned)n;
}

// ============================================================
// K1: fused prep (grid-704 layout, proven).
// ============================================================
__device__ __forceinline__ void split8(const float* src, __half* hi, __half* lo,
                                       float* sumsq) {
    float4 va = ((const float4*)src)[0];
    float4 vb = ((const float4*)src)[1];
    float f[8] = {va.x, va.y, va.z, va.w, vb.x, vb.y, vb.z, vb.w};
    __half2 h2[4], l2[4];
    float s = 0.0f;
    #pragma unroll
    for (int i = 0; i < 4; i++) {
        float a = f[2 * i], b = f[2 * i + 1];
        s += a * a + b * b;
        float ha = __half2float(__float2half_rn(a));
        float hb = __half2float(__float2half_rn(b));
        h2[i] = __floats2half2_rn(ha, hb);
        l2[i] = __floats2half2_rn(a - ha, b - hb);
    }
    *(uint4*)hi = *(uint4*)h2;
    *(uint4*)lo = *(uint4*)l2;
    if (sumsq) *sumsq = s;
}

__global__ void __launch_bounds__(256) k_prep_all(const float* __restrict__ x,
                                                  const float* __restrict__ w,
                                                  const int* __restrict__ iter) {
    int bid = blockIdx.x;
    int t = threadIdx.x;
    int warp = t >> 5, lane = t & 31;

    if (bid < 512) {                       // w rows: split + w2
        int n = bid * 8 + warp;
        int c = lane * 8;
        float s;
        split8(w + (size_t)n * FEATS + c, g_wh + n * FEATS + c,
               g_wl + n * FEATS + c, &s);
        #pragma unroll
        for (int o = 16; o; o >>= 1) s += __shfl_xor_sync(0xFFFFFFFFu, s, o);
        if (lane == 0) g_w2[n] = s;
    } else if (bid < 640) {                // x rows: split
        int r = (bid - 512) * 8 + warp;
        int c = lane * 8;
        split8(x + (size_t)r * FEATS + c, g_xh + r * FEATS + c,
               g_xl + r * FEATS + c, nullptr);
    } else {                               // x transpose tiles
        __shared__ float s[64][65];
        int bx2 = bid - 640;
        if (bx2 < 4) {
            g_best[bx2 * 256 + t] = 0xFFFFFFFFFFFFFFFFull;
            if (bx2 == 0 && t == 0) {
                float lambda_g = TOTAL_ITER_F / SIGMA_F;
                float decay    = expf(-(float)iter[0] / lambda_g);
                float radius   = SIGMA_F * decay + 1e-6f;
                g_params[0] = 0.5f * decay;
                g_params[1] = 1.0f / (2.0f * radius * radius);
                g_params[2] = radius * radius;
            }
        }
        int b0 = (bx2 >> 2) * 64, d0 = (bx2 & 3) * 64;
        #pragma unroll
        for (int q = 0; q < 16; q++) {
            int e = q * 256 + t;
            int br = e >> 6, dc = e & 63;
            s[br][dc] = x[(size_t)(b0 + br) * FEATS + d0 + dc];
        }
        __syncthreads();
        #pragma unroll
        for (int q = 0; q < 16; q++) {
            int e = q * 256 + t;
            int dr = e >> 6, bc = e & 63;
            g_xt[(size_t)(d0 + dr) * BATCH + b0 + bc] = __float2half_rn(s[bc][dr]);
        }
    }
}

// ============================================================
// K2: BMU GEMM via HMMA. NEW staging: 8 k-chunks of 32 elems,
// each co-stages {xh, xl, wh, wl} tiles once (row = 64B + 16B
// skew = 80B stride) and runs 3 term-passes (hh, hl, lh) on the
// staged data. -40% cp.async traffic, 8 barriers vs 12. Same
// warp layout (4m x 2n, 32m x 64n), same epilogue, 2 CTAs/SM.
// ============================================================
#define BT_STR 80                      // tile row stride (64B + 16B skew)
#define BT_SZ  (128 * BT_STR)          // one tile: 10240 B
#define BBUF_SZ (4 * BT_SZ)            // 4 tiles: 40960 B
#define BOFF_T 1024                    // tiles start (after w2s)
#define SM_BMU (BOFF_T + 2 * BBUF_SZ)  // 82944 B

__device__ __forceinline__ void stage_bmu(uint32_t sb, int buf, int ch,
                                          int m0, int n0, int t) {
    int kk = ch * 32;
    uint32_t base = sb + BOFF_T + buf * BBUF_SZ;
    // 4 tiles x 128 rows x 4 granules = 2048 granules; 8 per thread
    #pragma unroll
    for (int q = 0; q < 8; q++) {
        int g = t + 256 * q;
        int tile = g >> 9;             // 0:xh 1:xl 2:wh 3:wl
        int gi = g & 511;
        int r = gi >> 2, c = gi & 3;
        const __half* src;
        size_t row;
        if (tile == 0)      { src = g_xh; row = (size_t)(m0 + r); }
        else if (tile == 1) { src = g_xl; row = (size_t)(m0 + r); }
        else if (tile == 2) { src = g_wh; row = (size_t)(n0 + r); }
        else                { src = g_wl; row = (size_t)(n0 + r); }
        cp16(base + tile * BT_SZ + r * BT_STR + c * 16,
             src + row * FEATS + kk + c * 8);
    }
    CP_COMMIT();
}

__global__ void __launch_bounds__(256, 2) k_bmu() {
    extern __shared__ char sm[];
    uint32_t sb = smem_u32(sm);
    float* w2s = (float*)sm;
    int t = threadIdx.x, lane = t & 31, warp = t >> 5;
    int wm = warp >> 1, wn = warp & 1;     // 4m x 2n warp grid
    int n0 = blockIdx.x * 128;
    int m0 = blockIdx.y * 128;

    if (t < 128) w2s[t] = g_w2[n0 + t];

    float c[2][8][4];
    #pragma unroll
    for (int i = 0; i < 2; i++)
        #pragma unroll
        for (int j = 0; j < 8; j++)
            #pragma unroll
            for (int q = 0; q < 4; q++) c[i][j][q] = 0.0f;

    uint32_t aoff = (uint32_t)((lane & 15) * BT_STR + (lane >> 4) * 16);
    uint32_t boff = (uint32_t)(((lane & 7) + ((lane >> 4) << 3)) * BT_STR
                               + (((lane >> 3) & 1) << 4));

    stage_bmu(sb, 0, 0, m0, n0, t);
    for (int ch = 0; ch < 8; ch++) {
        CP_WAIT0();
        __syncthreads();   // tiles visible + prior-iter reads of buf^1 done
        if (ch + 1 < 8) stage_bmu(sb, (ch + 1) & 1, ch + 1, m0, n0, t);

        uint32_t tb = sb + BOFF_T + (ch & 1) * BBUF_SZ;
        // term t3: A tile {0:xh, 1:xh, 2:xl}, B tile {0:wh, 1:wl, 2:wh}
        #pragma unroll
        for (int t3 = 0; t3 < 3; t3++) {
            int atile = (t3 < 2) ? 0 : 1;
            int btile = (t3 == 1) ? 3 : 2;
            uint32_t Ab = tb + atile * BT_SZ + (wm * 32) * BT_STR + aoff;
            uint32_t Bb = tb + btile * BT_SZ + (wn * 64) * BT_STR + boff;
            #pragma unroll
            for (int k16 = 0; k16 < 2; k16++) {
                uint32_t a[2][4], b[4][4];
                #pragma unroll
                for (int im = 0; im < 2; im++)
                    ldsm4(a[im], Ab + im * 16 * BT_STR + k16 * 32);
                #pragma unroll
                for (int j2 = 0; j2 < 4; j2++)
                    ldsm4(b[j2], Bb + j2 * 16 * BT_STR + k16 * 32);
                #pragma unroll
                for (int im = 0; im < 2; im++)
                    #pragma unroll
                    for (int j2 = 0; j2 < 4; j2++) {
                        mma16816(c[im][2 * j2],     a[im], b[j2]);
                        mma16816(c[im][2 * j2 + 1], a[im], b[j2] + 2);
                    }
            }
        }
    }

    // fused argmin epilogue (unchanged)
    #pragma unroll
    for (int im = 0; im < 2; im++) {
        #pragma unroll
        for (int h = 0; h < 2; h++) {
            float best = __int_as_float(0x7F800000);
            int bestn = 0;
            #pragma unroll
            for (int j8 = 0; j8 < 8; j8++) {
                int nl = wn * 64 + j8 * 8 + 2 * (lane & 3);
                float v0 = w2s[nl]     - 2.0f * c[im][j8][2 * h];
                float v1 = w2s[nl + 1] - 2.0f * c[im][j8][2 * h + 1];
                if (v0 < best) { best = v0; bestn = nl; }
                if (v1 < best) { best = v1; bestn = nl + 1; }
            }
            #pragma unroll
            for (int o = 1; o <= 2; o <<= 1) {
                float od = __shfl_xor_sync(0xFFFFFFFFu, best, o);
                int   on = __shfl_xor_sync(0xFFFFFFFFu, bestn, o);
                if (od < best || (od == best && on < bestn)) { best = od; bestn = on; }
            }
            if ((lane & 3) == 0) {
                int m = m0 + wm * 32 + im * 16 + h * 8 + (lane >> 2);
                atomicMin(&g_best[m], packkey(best, n0 + bestn));
            }
        }
    }
}

// ============================================================
// K3: update GEMM (R16 champion, unchanged): 32n x 128d, grid 256,
// 2 CTAs/SM, 128-b chunks (8 chunks), gen-AHEAD vectorized gen_L.
// ============================================================
#define UXSZ (128 * 272)
#define ULSZ (32 * 272)
#define UOFF_X 0
#define UOFF_L (2 * UXSZ)
#define UOFF_SP (UOFF_L + 2 * ULSZ)
#define UOFF_SS (UOFF_SP + 1024)
#define SM_UPD (UOFF_SS + 128)

__global__ void __launch_bounds__(256, 2) k_update(const float* __restrict__ w,
                                                   float* __restrict__ out,
                                                   int out_size) {
    extern __shared__ char sm[];
    uint32_t sb = smem_u32(sm);
    float* s_part = (float*)(sm + UOFF_SP);
    float* s_sm   = (float*)(sm + UOFF_SS);

    int t = threadIdx.x, lane = t & 31, warp = t >> 5;
    int wn = warp >> 2, wd = warp & 3;     // 2n x 4d warp grid
    int bx = blockIdx.x;
    int n0 = (bx >> 1) * 32;
    int d0 = (bx & 1) * 128;

    float lr = g_params[0], inv2r2 = g_params[1], r2 = g_params[2];

    int n_l = t & 31;
    int gn = n0 + n_l;
    int ni = gn >> 6, nj = gn & 63;
    int bgrp = t >> 5;
    float s_local = 0.0f;

    float c[4][4];
    #pragma unroll
    for (int j = 0; j < 4; j++)
        #pragma unroll
        for (int q = 0; q < 4; q++) c[j][q] = 0.0f;

    uint32_t aoff = (uint32_t)((lane & 15) * 272 + (lane >> 4) * 16);
    uint32_t boff = (uint32_t)(((lane & 7) + ((lane >> 4) << 3)) * 272
                               + (((lane >> 3) & 1) << 4));

    auto gen_L = [&](int ch, int buf) {
        __half* Lrow = (__half*)(sm + UOFF_L + buf * ULSZ) + n_l * 136 + bgrp * 16;
        const uint4* gp = (const uint4*)&g_best[ch * 128 + bgrp * 16];
        __half2 hv[8];
        #pragma unroll
        for (int e = 0; e < 8; e++) {
            uint4 qq = gp[e];
            int b0 = (int)qq.x, b1 = (int)qq.z;
            float di0 = (float)(ni - (b0 >> 6)), dj0 = (float)(nj - (b0 & 63));
            float di1 = (float)(ni - (b1 >> 6)), dj1 = (float)(nj - (b1 & 63));
            float d20 = di0 * di0 + dj0 * dj0;
            float d21 = di1 * di1 + dj1 * dj1;
            float v0 = (d20 <= r2) ? lr * __expf(-d20 * inv2r2) : 0.0f;
            float v1 = (d21 <= r2) ? lr * __expf(-d21 * inv2r2) : 0.0f;
            s_local += v0 + v1;
            hv[e] = __floats2half2_rn(v0, v1);
        }
        ((uint4*)Lrow)[0] = ((uint4*)hv)[0];
        ((uint4*)Lrow)[1] = ((uint4*)hv)[1];
    };

    auto stage_x = [&](int ch, int buf) {
        uint32_t xdst = sb + UOFF_X + buf * UXSZ;
        #pragma unroll
        for (int q = 0; q < 8; q++) {
            int g = t + 256 * q; int r = g >> 4, cc = g & 15;
            cp16(xdst + r * 272 + cc * 16,
                 g_xt + (size_t)(d0 + r) * BATCH + ch * 128 + cc * 8);
        }
        CP_COMMIT();
    };

    stage_x(0, 0);
    gen_L(0, 0);

    for (int ch = 0; ch < 8; ch++) {
        CP_WAIT0();
        __syncthreads();
        if (ch + 1 < 8) {
            stage_x(ch + 1, (ch + 1) & 1);
            gen_L(ch + 1, (ch + 1) & 1);
        }

        uint32_t Ab = sb + UOFF_L + (ch & 1) * ULSZ + (wn * 16) * 272 + aoff;
        uint32_t Bb = sb + UOFF_X + (ch & 1) * UXSZ + (wd * 32) * 272 + boff;
        #pragma unroll
        for (int k16 = 0; k16 < 8; k16++) {
            uint32_t a[4], b[2][4];
            ldsm4(a, Ab + k16 * 32);
            #pragma unroll
            for (int j2 = 0; j2 < 2; j2++)
                ldsm4(b[j2], Bb + j2 * 16 * 272 + k16 * 32);
            #pragma unroll
            for (int jd = 0; jd < 4; jd++)
                mma16816(c[jd], a, b[jd >> 1] + (jd & 1) * 2);
        }
    }

    s_part[t] = s_local;
    __syncthreads();
    if (t < 32) {
        float s = 0.0f;
        #pragma unroll
        for (int g = 0; g < 8; g++) s += s_part[t + 32 * g];
        s_sm[t] = s;
    }
    __syncthreads();

    const float invB = 1.0f / (float)BATCH;
    #pragma unroll
    for (int h = 0; h < 2; h++) {
        int nl = wn * 16 + h * 8 + (lane >> 2);
        int n = n0 + nl;
        float s = s_sm[nl];
        #pragma unroll
        for (int jd = 0; jd < 4; jd++) {
            int d = d0 + wd * 32 + jd * 8 + 2 * (lane & 3);
            size_t idx = (size_t)n * FEATS + d;
            float2 wv = *(const float2*)&w[idx];
            float a0 = c[jd][2 * h], a1 = c[jd][2 * h + 1];
            float2 o;
            o.x = wv.x + (a0 - s * wv.x) * invB;
            o.y = wv.y + (a1 - s * wv.y) * invB;
            *(float2*)&out[idx] = o;
        }
    }

    if (bx < 4 && out_size >= NODES * FEATS + BATCH) {
        int b = bx * 256 + t;
        out[NODES * FEATS + b] =
            (float)(unsigned)(g_best[b] & 0xFFFFFFFFull);
    }
}

// ============================================================
extern "C" void kernel_launch(void* const* d_in, const int* in_sizes, int n_in,
                              void* d_out, int out_size) {
    const float* x = nullptr;
    const float* w = nullptr;
    const int* iter = nullptr;
    for (int i = 0; i < n_in; i++) {
        if (in_sizes[i] == BATCH * FEATS)      x = (const float*)d_in[i];
        else if (in_sizes[i] == NODES * FEATS) w = (const float*)d_in[i];
        else if (in_sizes[i] == 1)             iter = (const int*)d_in[i];
    }
    float* out = (float*)d_out;

    cudaFuncSetAttribute(k_bmu, cudaFuncAttributeMaxDynamicSharedMemorySize, SM_BMU);
    cudaFuncSetAttribute(k_update, cudaFuncAttributeMaxDynamicSharedMemorySize, SM_UPD);

    k_prep_all<<<704, 256>>>(x, w, iter);
    dim3 gb(NODES / 128, BATCH / 128);
    k_bmu<<<gb, 256, SM_BMU>>>();
    k_update<<<(NODES / 32) * (FEATS / 128), 256, SM_UPD>>>(w, out, out_size);
}